// round 3
// baseline (speedup 1.0000x reference)
#include <cuda_runtime.h>

#define CIN   6
#define COUT  16
#define FS    5
#define HIN   512
#define WIN   512
#define HOUT  508
#define WOUT  508
#define BATCHN 32

// Dense [ky][kx][ci][co] kernel with structural zeros, built per launch.
__device__ float g_Wd[FS * FS * CIN * COUT];

__global__ void build_weights(const float* __restrict__ w3,
                              const float* __restrict__ w4,
                              const float* __restrict__ w44,
                              const float* __restrict__ w6) {
    int idx = blockIdx.x * blockDim.x + threadIdx.x;
    if (idx >= FS * FS * CIN * COUT) return;
    int co = idx % COUT;
    int ci = (idx / COUT) % CIN;
    int kk = idx / (COUT * CIN);   // ky*5 + kx
    float v = 0.f;
    if (co < 6) {
        int i = co;
        #pragma unroll
        for (int m = 0; m < 3; ++m)
            if (ci == (i + m) % 6) v = w3[(kk * 3 + m) * 6 + i];
    } else if (co < 12) {
        int k = co - 6;
        #pragma unroll
        for (int m = 0; m < 4; ++m)
            if (ci == (k + m) % 6) v = w4[(kk * 4 + m) * 6 + k];
    } else if (co < 15) {
        int k = co - 12;
        const int off[4] = {0, 1, 3, 4};
        #pragma unroll
        for (int m = 0; m < 4; ++m)
            if (ci == (k + off[m]) % 6) v = w44[(kk * 4 + m) * 3 + k];
    } else {
        v = w6[kk * 6 + ci];
    }
    g_Wd[idx] = v;
}

// ---- packed f32x2 helpers (Blackwell FFMA2 only reachable via PTX) ----
__device__ __forceinline__ unsigned long long pack2(float lo, float hi) {
    unsigned long long r;
    asm("mov.b64 %0, {%1, %2};" : "=l"(r) : "f"(lo), "f"(hi));
    return r;
}
__device__ __forceinline__ void ffma2(unsigned long long& acc,
                                      unsigned long long a,
                                      unsigned long long b) {
    asm("fma.rn.f32x2 %0, %1, %2, %0;" : "+l"(acc) : "l"(a), "l"(b));
}

// Tile: 8 rows x 64 cols of output per 256-thread block.
// Threads: tx (64 cols) x coh (2 cout-halves) x ty (2 row-groups of 4 rows).
// Each thread: 4 rows x 1 col x 8 couts = 16 f32x2 accumulators.
#define TH 8
#define TW 64
#define IH (TH + 4)   // 12
#define IW (TW + 4)   // 68

__global__ __launch_bounds__(256, 3) void conv_dense_kernel(
    const float* __restrict__ in,
    const float* __restrict__ bias,
    float* __restrict__ out) {

    __shared__ float s_in[CIN][IH][IW];                       // 19584 B
    __shared__ __align__(16) float s_w[FS * FS * CIN][COUT];  // 9600 B
    __shared__ float s_bias[COUT];

    const int tid = threadIdx.x;
    const int b  = blockIdx.z;
    const int y0 = blockIdx.y * TH;
    const int x0 = blockIdx.x * TW;

    // Stage weights + bias
    for (int i = tid; i < FS * FS * CIN * COUT; i += 256)
        ((float*)s_w)[i] = g_Wd[i];
    if (tid < COUT) s_bias[tid] = bias[tid];

    // Stage input tile (coalesced LDG), scatter into [ci][row][col].
    const float* inb = in + (long long)b * (HIN * WIN * CIN);
    for (int idx = tid; idx < IH * IW * CIN; idx += 256) {
        int r  = idx / (IW * CIN);
        int t  = idx - r * (IW * CIN);
        int c  = t / CIN;
        int ci = t - c * CIN;
        int gy = y0 + r, gx = x0 + c;
        float v = 0.f;
        if (gy < HIN && gx < WIN)
            v = inb[(gy * WIN + gx) * CIN + ci];
        s_in[ci][r][c] = v;
    }
    __syncthreads();

    const int tx  = tid & 63;          // output column in tile (uniform warp run)
    const int coh = (tid >> 6) & 1;    // cout half: 0 -> co 0..7, 1 -> co 8..15
    const int ty  = tid >> 7;          // row group
    const int ry  = ty * 4;

    // acc[p][j]: (row ry+p, couts coh*8 + 2j, +1)
    unsigned long long acc[4][4];
    #pragma unroll
    for (int j = 0; j < 4; ++j) {
        unsigned long long bj = pack2(s_bias[coh * 8 + 2 * j],
                                      s_bias[coh * 8 + 2 * j + 1]);
        #pragma unroll
        for (int p = 0; p < 4; ++p) acc[p][j] = bj;
    }

    const float* a_base = &s_in[0][ry][tx];
    const float* w_base = &s_w[0][0] + coh * 8;   // this half's 8 couts

    #pragma unroll 1
    for (int ky = 0; ky < 5; ++ky) {
        const float* a_ky = a_base + ky * IW;
        const float* w_ky = w_base + ky * (5 * CIN * COUT);
        #pragma unroll
        for (int kx = 0; kx < 5; ++kx) {
            #pragma unroll
            for (int ci = 0; ci < 6; ++ci) {
                // 4 scalar a-loads (conflict-free, 128 B/warp) + dup packs
                float v0 = a_ky[(ci * IH + 0) * IW + kx];
                float v1 = a_ky[(ci * IH + 1) * IW + kx];
                float v2 = a_ky[(ci * IH + 2) * IW + kx];
                float v3 = a_ky[(ci * IH + 3) * IW + kx];
                unsigned long long a0 = pack2(v0, v0);
                unsigned long long a1 = pack2(v1, v1);
                unsigned long long a2 = pack2(v2, v2);
                unsigned long long a3 = pack2(v3, v3);
                // 8 couts = 2 LDS.128 broadcast
                const ulonglong2* wq =
                    (const ulonglong2*)(w_ky + (kx * CIN + ci) * COUT);
                ulonglong2 wA = wq[0];   // co pairs 0,1
                ulonglong2 wB = wq[1];   // co pairs 2,3

                ffma2(acc[0][0], a0, wA.x); ffma2(acc[1][0], a1, wA.x);
                ffma2(acc[2][0], a2, wA.x); ffma2(acc[3][0], a3, wA.x);
                ffma2(acc[0][1], a0, wA.y); ffma2(acc[1][1], a1, wA.y);
                ffma2(acc[2][1], a2, wA.y); ffma2(acc[3][1], a3, wA.y);
                ffma2(acc[0][2], a0, wB.x); ffma2(acc[1][2], a1, wB.x);
                ffma2(acc[2][2], a2, wB.x); ffma2(acc[3][2], a3, wB.x);
                ffma2(acc[0][3], a0, wB.y); ffma2(acc[1][3], a1, wB.y);
                ffma2(acc[2][3], a2, wB.y); ffma2(acc[3][3], a3, wB.y);
            }
        }
    }

    // Store: 8 contiguous fp32 per (pixel, half) -> 2x STG.128
    const int gx = x0 + tx;
    if (gx < WOUT) {
        #pragma unroll
        for (int p = 0; p < 4; ++p) {
            int gy = y0 + ry + p;
            if (gy < HOUT) {
                ulonglong2* op = (ulonglong2*)(out +
                    ((long long)(b * HOUT + gy) * WOUT + gx) * COUT + coh * 8);
                ulonglong2 u0, u1;
                u0.x = acc[p][0]; u0.y = acc[p][1];
                u1.x = acc[p][2]; u1.y = acc[p][3];
                op[0] = u0;
                op[1] = u1;
            }
        }
    }
}

extern "C" void kernel_launch(void* const* d_in, const int* in_sizes, int n_in,
                              void* d_out, int out_size) {
    const float* inputs = (const float*)d_in[0];
    const float* w3     = (const float*)d_in[1];
    const float* w4     = (const float*)d_in[2];
    const float* w44    = (const float*)d_in[3];
    const float* w6     = (const float*)d_in[4];
    const float* bias   = (const float*)d_in[5];

    build_weights<<<(FS * FS * CIN * COUT + 255) / 256, 256>>>(w3, w4, w44, w6);

    dim3 grid((WOUT + TW - 1) / TW, (HOUT + TH - 1) / TH, BATCHN);
    conv_dense_kernel<<<grid, 256>>>(inputs, bias, (float*)d_out);
}

// round 4
// speedup vs baseline: 1.1982x; 1.1982x over previous
#include <cuda_runtime.h>

#define CIN   6
#define COUT  16
#define FS    5
#define HIN   512
#define WIN   512
#define HOUT  508
#define WOUT  508
#define BATCHN 32

// Dense [ky][kx][ci][co] kernel with structural zeros, built per launch.
__device__ float g_Wd[FS * FS * CIN * COUT];

__global__ void build_weights(const float* __restrict__ w3,
                              const float* __restrict__ w4,
                              const float* __restrict__ w44,
                              const float* __restrict__ w6) {
    int idx = blockIdx.x * blockDim.x + threadIdx.x;
    if (idx >= FS * FS * CIN * COUT) return;
    int co = idx % COUT;
    int ci = (idx / COUT) % CIN;
    int kk = idx / (COUT * CIN);   // ky*5 + kx
    float v = 0.f;
    if (co < 6) {
        int i = co;
        #pragma unroll
        for (int m = 0; m < 3; ++m)
            if (ci == (i + m) % 6) v = w3[(kk * 3 + m) * 6 + i];
    } else if (co < 12) {
        int k = co - 6;
        #pragma unroll
        for (int m = 0; m < 4; ++m)
            if (ci == (k + m) % 6) v = w4[(kk * 4 + m) * 6 + k];
    } else if (co < 15) {
        int k = co - 12;
        const int off[4] = {0, 1, 3, 4};
        #pragma unroll
        for (int m = 0; m < 4; ++m)
            if (ci == (k + off[m]) % 6) v = w44[(kk * 4 + m) * 3 + k];
    } else {
        v = w6[kk * 6 + ci];
    }
    g_Wd[idx] = v;
}

// ---- packed f32x2 helpers (Blackwell FFMA2 only reachable via PTX) ----
__device__ __forceinline__ unsigned long long pack2(float lo, float hi) {
    unsigned long long r;
    asm("mov.b64 %0, {%1, %2};" : "=l"(r) : "f"(lo), "f"(hi));
    return r;
}
__device__ __forceinline__ void ffma2(unsigned long long& acc,
                                      unsigned long long a,
                                      unsigned long long b) {
    asm("fma.rn.f32x2 %0, %1, %2, %0;" : "+l"(acc) : "l"(a), "l"(b));
}

// Tile: 20 rows x 64 cols per 256-thread block.
// Threads: tx = tid&63 (column), ty = tid>>6 (4 groups of 5 rows).
// Each thread: 5 rows x 1 col x 16 couts = 40 f32x2 accumulators.
#define RPT 5          // rows per thread
#define TH  (RPT * 4)  // 20
#define TW  64
#define IH  (TH + 4)   // 24
#define IW  (TW + 4)   // 68

__global__ __launch_bounds__(256, 2) void conv_dense_kernel(
    const float* __restrict__ in,
    const float* __restrict__ bias,
    float* __restrict__ out) {

    __shared__ float s_in[CIN][IH][IW];                       // 39168 B
    __shared__ __align__(16) float s_w[FS * FS * CIN][COUT];  // 9600 B
    __shared__ float s_bias[COUT];

    const int tid = threadIdx.x;
    const int b  = blockIdx.z;
    const int y0 = blockIdx.y * TH;
    const int x0 = blockIdx.x * TW;

    // Stage weights + bias
    for (int i = tid; i < FS * FS * CIN * COUT; i += 256)
        ((float*)s_w)[i] = g_Wd[i];
    if (tid < COUT) s_bias[tid] = bias[tid];

    // Stage input tile (coalesced LDG), scatter into [ci][row][col].
    const float* inb = in + (long long)b * (HIN * WIN * CIN);
    for (int idx = tid; idx < IH * IW * CIN; idx += 256) {
        int r  = idx / (IW * CIN);
        int t  = idx - r * (IW * CIN);
        int c  = t / CIN;
        int ci = t - c * CIN;
        int gy = y0 + r, gx = x0 + c;
        float v = 0.f;
        if (gy < HIN && gx < WIN)
            v = inb[(gy * WIN + gx) * CIN + ci];
        s_in[ci][r][c] = v;
    }
    __syncthreads();

    const int tx = tid & 63;   // column (lanes consecutive -> conflict-free LDS)
    const int ty = tid >> 6;   // row group
    const int ry = ty * RPT;   // first of 5 rows

    // acc[p][j]: (row ry+p, couts 2j, 2j+1)
    unsigned long long acc[RPT][8];
    #pragma unroll
    for (int j = 0; j < 8; ++j) {
        unsigned long long bj = pack2(s_bias[2 * j], s_bias[2 * j + 1]);
        #pragma unroll
        for (int p = 0; p < RPT; ++p) acc[p][j] = bj;
    }

    const float* a_base = &s_in[0][ry][tx];

    #pragma unroll 1
    for (int ky = 0; ky < 5; ++ky) {
        const float* a_ky = a_base + ky * IW;
        const float* w_ky = &s_w[ky * (5 * CIN)][0];
        #pragma unroll
        for (int kx = 0; kx < 5; ++kx) {
            #pragma unroll
            for (int ci = 0; ci < 6; ++ci) {
                // 5 scalar a-loads (1 wavefront each) + packs (alu pipe)
                unsigned long long a[RPT];
                #pragma unroll
                for (int p = 0; p < RPT; ++p) {
                    float v = a_ky[(ci * IH + p) * IW + kx];
                    a[p] = pack2(v, v);
                }
                // 16 couts = 4x LDS.128 broadcast (1 wavefront each)
                const ulonglong2* wq =
                    (const ulonglong2*)&w_ky[(kx * CIN + ci) * COUT];
                ulonglong2 wA = wq[0];   // co 0..3
                ulonglong2 wB = wq[1];   // co 4..7
                ulonglong2 wC = wq[2];   // co 8..11
                ulonglong2 wD = wq[3];   // co 12..15

                #pragma unroll
                for (int p = 0; p < RPT; ++p) {
                    ffma2(acc[p][0], a[p], wA.x);
                    ffma2(acc[p][1], a[p], wA.y);
                    ffma2(acc[p][2], a[p], wB.x);
                    ffma2(acc[p][3], a[p], wB.y);
                    ffma2(acc[p][4], a[p], wC.x);
                    ffma2(acc[p][5], a[p], wC.y);
                    ffma2(acc[p][6], a[p], wD.x);
                    ffma2(acc[p][7], a[p], wD.y);
                }
            }
        }
    }

    // Store: 16 contiguous fp32 per pixel -> 4x STG.128
    const int gx = x0 + tx;
    if (gx < WOUT) {
        #pragma unroll
        for (int p = 0; p < RPT; ++p) {
            int gy = y0 + ry + p;
            if (gy < HOUT) {
                ulonglong2* op = (ulonglong2*)(out +
                    ((long long)(b * HOUT + gy) * WOUT + gx) * COUT);
                #pragma unroll
                for (int q = 0; q < 4; ++q) {
                    ulonglong2 u;
                    u.x = acc[p][2 * q];
                    u.y = acc[p][2 * q + 1];
                    op[q] = u;
                }
            }
        }
    }
}

extern "C" void kernel_launch(void* const* d_in, const int* in_sizes, int n_in,
                              void* d_out, int out_size) {
    const float* inputs = (const float*)d_in[0];
    const float* w3     = (const float*)d_in[1];
    const float* w4     = (const float*)d_in[2];
    const float* w44    = (const float*)d_in[3];
    const float* w6     = (const float*)d_in[4];
    const float* bias   = (const float*)d_in[5];

    build_weights<<<(FS * FS * CIN * COUT + 255) / 256, 256>>>(w3, w4, w44, w6);

    dim3 grid((WOUT + TW - 1) / TW, (HOUT + TH - 1) / TH, BATCHN);
    conv_dense_kernel<<<grid, 256>>>(inputs, bias, (float*)d_out);
}

// round 6
// speedup vs baseline: 2.0298x; 1.6940x over previous
#include <cuda_runtime.h>
#include <cstdint>

#define CIN   6
#define COUT  16
#define FS    5
#define HIN   512
#define WIN   512
#define HOUT  508
#define WOUT  508
#define BATCHN 32

// ---- dense weights (fp32), built per launch ----
__device__ float g_Wd[FS * FS * CIN * COUT];

__global__ void build_weights(const float* __restrict__ w3,
                              const float* __restrict__ w4,
                              const float* __restrict__ w44,
                              const float* __restrict__ w6) {
    int idx = blockIdx.x * blockDim.x + threadIdx.x;
    if (idx >= FS * FS * CIN * COUT) return;
    int co = idx % COUT;
    int ci = (idx / COUT) % CIN;
    int kk = idx / (COUT * CIN);
    float v = 0.f;
    if (co < 6) {
        int i = co;
        #pragma unroll
        for (int m = 0; m < 3; ++m)
            if (ci == (i + m) % 6) v = w3[(kk * 3 + m) * 6 + i];
    } else if (co < 12) {
        int k = co - 6;
        #pragma unroll
        for (int m = 0; m < 4; ++m)
            if (ci == (k + m) % 6) v = w4[(kk * 4 + m) * 6 + k];
    } else if (co < 15) {
        int k = co - 12;
        const int off[4] = {0, 1, 3, 4};
        #pragma unroll
        for (int m = 0; m < 4; ++m)
            if (ci == (k + off[m]) % 6) v = w44[(kk * 4 + m) * 3 + k];
    } else {
        v = w6[kk * 6 + ci];
    }
    g_Wd[idx] = v;
}

// ============== mma.sync tf32 conv (baseline PTX, tensor pipe) ==============
// D^T form: per mma, D[16 couts][8 pixels], A = weights (m16 x k8),
// B = input (k8 x n8). K slots are ci permuted [0,4,1,5,2,6,3,7] so each
// thread's (k, k+4) pair is one LDS.64. Slots 5,7 are zero (ci pad).
//
// CTA: 256 threads = 8 warps; tile = 8 output rows x 64 output cols.
// Warp w owns output row y0+w: 8 n-chunks of 8 px, D regs accumulate
// across all 25 taps.

#define TW    64
#define RT    8
#define AROWS (RT + 4)    // 12
#define ACOLS (TW + 4)    // 68

__device__ __forceinline__ uint32_t cvt_tf32(float f) {
    uint32_t u;
    asm("cvt.rna.tf32.f32 %0, %1;" : "=r"(u) : "f"(f));
    return u;
}

__device__ __forceinline__ void mma_tf32(float d[4],
                                         uint32_t a0, uint32_t a1,
                                         uint32_t a2, uint32_t a3,
                                         uint32_t b0, uint32_t b1) {
    asm volatile(
        "mma.sync.aligned.m16n8k8.row.col.f32.tf32.tf32.f32 "
        "{%0,%1,%2,%3}, {%4,%5,%6,%7}, {%8,%9}, {%0,%1,%2,%3};"
        : "+f"(d[0]), "+f"(d[1]), "+f"(d[2]), "+f"(d[3])
        : "r"(a0), "r"(a1), "r"(a2), "r"(a3), "r"(b0), "r"(b1));
}

__global__ __launch_bounds__(256, 2) void conv_mma_kernel(
    const float* __restrict__ in,
    const float* __restrict__ bias,
    float* __restrict__ out) {

    __shared__ uint32_t s_in[AROWS][ACOLS][8];   // 26112 B, tf32 bits
    __shared__ uint32_t s_w[25][COUT][8];        // 12800 B, tf32 bits
    __shared__ float s_bias[COUT];

    const int tid = threadIdx.x;
    const int b  = blockIdx.z;
    const int y0 = blockIdx.y * RT;
    const int x0 = blockIdx.x * TW;

    // ---- stage weights: permuted K slots, zero pad slots 5,7 ----
    for (int i = tid; i < 25 * COUT; i += 256) {
        int tap = i / COUT, co = i % COUT;
        s_w[tap][co][5] = 0;
        s_w[tap][co][7] = 0;
    }
    for (int i = tid; i < 25 * COUT * CIN; i += 256) {
        int tap = i / (COUT * CIN);
        int r   = i % (COUT * CIN);
        int co  = r / CIN;
        int ci  = r % CIN;
        int slot = 2 * (ci & 3) + (ci >> 2);
        s_w[tap][co][slot] = cvt_tf32(g_Wd[(tap * CIN + ci) * COUT + co]);
    }
    if (tid < COUT) s_bias[tid] = bias[tid];

    // ---- stage input tile: [row][col][slot], zero pad + boundary zeros ----
    for (int i = tid; i < AROWS * ACOLS; i += 256) {
        int r = i / ACOLS, c = i % ACOLS;
        s_in[r][c][5] = 0;
        s_in[r][c][7] = 0;
    }
    const float* inb = in + (long long)b * (HIN * WIN * CIN);
    for (int i = tid; i < AROWS * ACOLS * CIN; i += 256) {
        int r   = i / (ACOLS * CIN);
        int rem = i - r * (ACOLS * CIN);
        int c   = rem / CIN;
        int ci  = rem - c * CIN;
        int gy = y0 + r, gx = x0 + c;
        float v = 0.f;
        if (gy < HIN && gx < WIN)
            v = inb[(gy * WIN + gx) * CIN + ci];
        int slot = 2 * (ci & 3) + (ci >> 2);
        s_in[r][c][slot] = cvt_tf32(v);
    }
    __syncthreads();

    // ---- per-warp MMA mainloop ----
    const int w    = tid >> 5;    // warp = output row within tile
    const int lane = tid & 31;
    const int g    = lane >> 2;   // group id: A rows (co g, g+8); B col (px g)
    const int tq   = lane & 3;    // thread-in-group: K positions tq, tq+4

    float d[8][4];
    #pragma unroll
    for (int n = 0; n < 8; ++n)
        #pragma unroll
        for (int q = 0; q < 4; ++q) d[n][q] = 0.f;

    #pragma unroll
    for (int ky = 0; ky < 5; ++ky) {
        const int row = w + ky;
        #pragma unroll
        for (int kx = 0; kx < 5; ++kx) {
            const int tap = ky * 5 + kx;
            // A fragment (weights): a0=(g,tq) a1=(g+8,tq) a2=(g,tq+4) a3=(g+8,tq+4)
            uint2 awLo = *(const uint2*)&s_w[tap][g][2 * tq];
            uint2 awHi = *(const uint2*)&s_w[tap][g + 8][2 * tq];
            #pragma unroll
            for (int n = 0; n < 8; ++n) {
                // B fragment (input): b0=(tq, px g), b1=(tq+4, px g)
                uint2 bv = *(const uint2*)&s_in[row][n * 8 + kx + g][2 * tq];
                mma_tf32(d[n], awLo.x, awHi.x, awLo.y, awHi.y, bv.x, bv.y);
            }
        }
    }

    // ---- epilogue: D(m=co, n=px) -> out[...][px][co], add bias ----
    const int gy = y0 + w;
    if (gy < HOUT) {
        const float bLo = s_bias[g];
        const float bHi = s_bias[g + 8];
        float* orow = out + ((long long)(b * HOUT + gy) * WOUT) * COUT;
        #pragma unroll
        for (int n = 0; n < 8; ++n) {
            int px = x0 + n * 8 + 2 * tq;
            if (px < WOUT) {
                float* p = orow + (long long)px * COUT;
                p[g]     = d[n][0] + bLo;
                p[g + 8] = d[n][2] + bHi;
            }
            if (px + 1 < WOUT) {
                float* p = orow + (long long)(px + 1) * COUT;
                p[g]     = d[n][1] + bLo;
                p[g + 8] = d[n][3] + bHi;
            }
        }
    }
}

extern "C" void kernel_launch(void* const* d_in, const int* in_sizes, int n_in,
                              void* d_out, int out_size) {
    const float* inputs = (const float*)d_in[0];
    const float* w3     = (const float*)d_in[1];
    const float* w4     = (const float*)d_in[2];
    const float* w44    = (const float*)d_in[3];
    const float* w6     = (const float*)d_in[4];
    const float* bias   = (const float*)d_in[5];

    build_weights<<<(FS * FS * CIN * COUT + 255) / 256, 256>>>(w3, w4, w44, w6);

    dim3 grid((WOUT + TW - 1) / TW,   // 8
              (HOUT + RT - 1) / RT,   // 64
              BATCHN);                 // 32
    conv_mma_kernel<<<grid, 256>>>(inputs, bias, (float*)d_out);
}